// round 3
// baseline (speedup 1.0000x reference)
#include <cuda_runtime.h>

// LGA: out[n,c,h,w] = sum_{i,j in 5x5} in1[n,c,h+i-2,w+j-2] * in2[n,i*5+j,h,w]
// Shapes fixed: in1 [4,32,384,768] f32, in2 [4,25,384,768] f32.
//
// Round-3 design: barrier-free, smem-free. Per-pixel 5x5 taps (50 floats for
// this thread's 2 output pixels) live in registers for the whole block and are
// reused across all 32 channels. Each thread reads its 5x6 input1 window
// directly from global memory as 3 overlapping LDG.64 per row; the block's
// 64x8 tile keeps those rows hot in L1 (each row is re-read by <=5 warps, all
// L1 hits after the first touch). No __syncthreads anywhere -> warps run as
// independent load/FMA streams.

#define NDIM 4
#define CDIM 32
#define HDIM 384
#define WDIM 768
#define KTAPS 25
#define PLANE (HDIM * WDIM)

#define TILE_W 64
#define TILE_H 8

__device__ __forceinline__ float2 ld2(const float* p) {
    return *(const float2*)p;
}

// 10 FMAs for one tap row: window x0..x5 = (L.x L.y M.x M.y R.x R.y),
// acc0 (pixel w0) uses x[j]*w.x, acc1 (pixel w0+1) uses x[j+1]*w.y.
__device__ __forceinline__ void row_fma(float2 L, float2 M, float2 R,
                                        const float2* wr,
                                        float& acc0, float& acc1) {
    acc0 = fmaf(L.x, wr[0].x, acc0);
    acc1 = fmaf(L.y, wr[0].y, acc1);
    acc0 = fmaf(L.y, wr[1].x, acc0);
    acc1 = fmaf(M.x, wr[1].y, acc1);
    acc0 = fmaf(M.x, wr[2].x, acc0);
    acc1 = fmaf(M.y, wr[2].y, acc1);
    acc0 = fmaf(M.y, wr[3].x, acc0);
    acc1 = fmaf(R.x, wr[3].y, acc1);
    acc0 = fmaf(R.x, wr[4].x, acc0);
    acc1 = fmaf(R.y, wr[4].y, acc1);
}

__global__ __launch_bounds__(256, 3)
void lga_kernel(const float* __restrict__ in1,
                const float* __restrict__ in2,
                float* __restrict__ out) {
    const int tx = threadIdx.x;            // 0..31
    const int ty = threadIdx.y;            // 0..7
    const int wbase = blockIdx.x * TILE_W;
    const int hbase = blockIdx.y * TILE_H;
    const int n = blockIdx.z;

    const int h = hbase + ty;              // output row
    const int w0 = wbase + 2 * tx;         // first of 2 output cols

    // ---- 25 per-pixel weight pairs into registers (input2 read exactly once,
    //      coalesced float2; .y lane is the weight for pixel w0+1) ----
    float2 wv[KTAPS];
    {
        const float* wp = in2 + ((size_t)n * KTAPS * HDIM + h) * WDIM + w0;
#pragma unroll
        for (int t = 0; t < KTAPS; t++)
            wv[t] = __ldcs((const float2*)(wp + (size_t)t * PLANE));
    }

    // base pointer of this thread's window (row h-2, col w0) for channel 0
    const float* bp = in1 + (size_t)n * CDIM * PLANE + (size_t)(h - 2) * WDIM + w0;
    float* po = out + (size_t)n * CDIM * PLANE + (size_t)h * WDIM + w0;

    const bool interior = (blockIdx.x != 0) && (blockIdx.x != gridDim.x - 1) &&
                          (blockIdx.y != 0) && (blockIdx.y != gridDim.y - 1);

    if (interior) {
        // ---- clean path: every load in-bounds, pure straight-line code ----
#pragma unroll 1
        for (int c = 0; c < CDIM; c++) {
            float acc0 = 0.0f, acc1 = 0.0f;
#pragma unroll
            for (int i = 0; i < 5; i++) {
                const float* rp = bp + i * WDIM;
                float2 L = ld2(rp - 2);
                float2 M = ld2(rp);
                float2 R = ld2(rp + 2);
                row_fma(L, M, R, &wv[5 * i], acc0, acc1);
            }
            __stcs((float2*)po, make_float2(acc0, acc1));
            bp += PLANE;
            po += PLANE;
        }
    } else {
        // ---- edge path: row guards are warp-uniform branches; the two
        //      horizontal halo pairs are lane-predicated (aligned even pairs,
        //      so both lanes of a pair share validity) ----
        const bool vL = (w0 >= 2);          // cols w0-2, w0-1 in-bounds
        const bool vR = (w0 + 3 < WDIM);    // cols w0+2, w0+3 in-bounds
#pragma unroll 1
        for (int c = 0; c < CDIM; c++) {
            float acc0 = 0.0f, acc1 = 0.0f;
#pragma unroll
            for (int i = 0; i < 5; i++) {
                const int r = h - 2 + i;
                if (r >= 0 && r < HDIM) {   // uniform across the warp
                    const float* rp = bp + i * WDIM;
                    float2 L = vL ? ld2(rp - 2) : make_float2(0.0f, 0.0f);
                    float2 M = ld2(rp);
                    float2 R = vR ? ld2(rp + 2) : make_float2(0.0f, 0.0f);
                    row_fma(L, M, R, &wv[5 * i], acc0, acc1);
                }
            }
            __stcs((float2*)po, make_float2(acc0, acc1));
            bp += PLANE;
            po += PLANE;
        }
    }
}

extern "C" void kernel_launch(void* const* d_in, const int* in_sizes, int n_in,
                              void* d_out, int out_size) {
    const float* in1 = (const float*)d_in[0];
    const float* in2 = (const float*)d_in[1];
    float* out = (float*)d_out;

    dim3 block(32, 8);
    dim3 grid(WDIM / TILE_W, HDIM / TILE_H, NDIM);  // 12 x 48 x 4
    lga_kernel<<<grid, block>>>(in1, in2, out);
}

// round 5
// speedup vs baseline: 2.1181x; 2.1181x over previous
#include <cuda_runtime.h>
#include <cstdint>

// LGA: out[n,c,h,w] = sum_{i,j in 5x5} in1[n,c,h+i-2,w+j-2] * in2[n,i*5+j,h,w]
// Shapes fixed: in1 [4,32,384,768] f32, in2 [4,25,384,768] f32.
//
// Round-5: cp.async (LDGSTS) 4-stage smem ring over the channel dim, with
// 16B-aligned staging (fixes round-4 misaligned-address fault).
//  - 50 per-pixel taps in registers, reused across all 32 channels.
//  - Per channel, a 72x12-float halo tile (cols wbase-4 .. wbase+67) is
//    fetched GMEM->SMEM with one 16B cp.async per thread (216 chunks / 256
//    threads), one commit group per channel. All chunks are 16B-aligned and
//    fully in- or out-of-bounds, so edges use the same path with src_size=0
//    zero-fill.
//  - wait_group 2 + 4-stage ring = ~3 iterations of prefetch slack, so the
//    per-channel barrier never waits on DRAM.

#define NDIM 4
#define CDIM 32
#define HDIM 384
#define WDIM 768
#define KTAPS 25
#define PLANE (HDIM * WDIM)

#define TILE_W 64
#define TILE_H 8
#define SROWS (TILE_H + 4)            // 12
#define SPITCH 72                     // floats per smem row (288B, 16B-mult)
#define STAGE_ELEMS (SROWS * SPITCH)  // 864 floats per stage
#define STAGES 4
#define CHUNKS_PER_ROW 18             // 18 x 16B = 72 floats
#define NCHUNK (SROWS * CHUNKS_PER_ROW)  // 216

__device__ __forceinline__ uint32_t smem_u32(const void* p) {
    return (uint32_t)__cvta_generic_to_shared(p);
}
// 16B cp.async with runtime source size (16 = copy, 0 = zero-fill)
__device__ __forceinline__ void cp_async16(uint32_t dst, const float* src, int sz) {
    asm volatile("cp.async.cg.shared.global [%0], [%1], 16, %2;\n"
                 :: "r"(dst), "l"(src), "r"(sz));
}
__device__ __forceinline__ void cp_commit() {
    asm volatile("cp.async.commit_group;\n" ::: "memory");
}
__device__ __forceinline__ void cp_wait2() {
    asm volatile("cp.async.wait_group 2;\n" ::: "memory");
}

__global__ __launch_bounds__(256, 3)
void lga_kernel(const float* __restrict__ in1,
                const float* __restrict__ in2,
                float* __restrict__ out) {
    __shared__ __align__(16) float ring[STAGES][STAGE_ELEMS];

    const int tx = threadIdx.x;            // 0..31
    const int ty = threadIdx.y;            // 0..7
    const int tid = ty * 32 + tx;
    const int wbase = blockIdx.x * TILE_W;
    const int hbase = blockIdx.y * TILE_H;
    const int n = blockIdx.z;

    const int h = hbase + ty;              // output row
    const int w0 = wbase + 2 * tx;         // first of 2 output cols

    // ---- 25 per-pixel weight pairs into registers (read exactly once) ----
    float2 wv[KTAPS];
    {
        const float* wp = in2 + ((size_t)n * KTAPS * HDIM + h) * WDIM + w0;
#pragma unroll
        for (int t = 0; t < KTAPS; t++)
            wv[t] = __ldcs((const float2*)(wp + (size_t)t * PLANE));
    }

    // ---- copy-role precompute: one 16B chunk per active thread ----
    const bool active = (tid < NCHUNK);
    const int  r   = tid / CHUNKS_PER_ROW;           // halo row 0..11
    const int  ch  = tid - r * CHUNKS_PER_ROW;       // chunk 0..17
    const int  gy  = hbase - 2 + r;
    const int  gx0 = wbase - 4 + 4 * ch;             // 16B-aligned column
    const bool valid = active && (gy >= 0) && (gy < HDIM) &&
                       (gx0 >= 0) && (gx0 + 3 < WDIM);
    const int  goff = valid ? (gy * WDIM + gx0) : 0; // clamp to keep addr legal
    const int  cpsz = valid ? 16 : 0;
    const int  soff = r * SPITCH + 4 * ch;

    const float* in1n = in1 + (size_t)n * CDIM * PLANE;
    float* po = out + (size_t)n * CDIM * PLANE + (size_t)h * WDIM + w0;

    uint32_t sdst[STAGES];
#pragma unroll
    for (int s = 0; s < STAGES; s++)
        sdst[s] = smem_u32(&ring[s][soff]);

    // issue the copy of channel c into stage s (one commit group per call)
    auto issue = [&](int c, int s) {
        if (active) cp_async16(sdst[s], in1n + (size_t)c * PLANE + goff, cpsz);
        cp_commit();
    };

    // ---- prologue: channels 0..2 in flight ----
    issue(0, 0);
    issue(1, 1);
    issue(2, 2);

#pragma unroll 1
    for (int c = 0; c < CDIM; c++) {
        const int s = c & (STAGES - 1);

        cp_wait2();          // group for channel c complete (>=2 still flying)
        __syncthreads();     // cross-thread visibility; also fences ring reuse

        // keep the pipeline full: fetch channel c+3 into the stage freed at c-1
        if (c + 3 < CDIM) issue(c + 3, (c + 3) & (STAGES - 1));
        else              cp_commit();   // empty group keeps wait-count math fixed

        // ---- compute 2 outputs of channel c from the ready stage ----
        // tile starts at column wbase-4, window for (w0-2..w0+3) -> +2*tx+2
        const float* basep = &ring[s][ty * SPITCH + 2 * tx + 2];
        float acc0 = 0.0f, acc1 = 0.0f;
#pragma unroll
        for (int i = 0; i < 5; i++) {
            float2 L = *(const float2*)(basep + i * SPITCH + 0);
            float2 M = *(const float2*)(basep + i * SPITCH + 2);
            float2 R = *(const float2*)(basep + i * SPITCH + 4);
            const float2* wr = &wv[5 * i];
            acc0 = fmaf(L.x, wr[0].x, acc0);
            acc1 = fmaf(L.y, wr[0].y, acc1);
            acc0 = fmaf(L.y, wr[1].x, acc0);
            acc1 = fmaf(M.x, wr[1].y, acc1);
            acc0 = fmaf(M.x, wr[2].x, acc0);
            acc1 = fmaf(M.y, wr[2].y, acc1);
            acc0 = fmaf(M.y, wr[3].x, acc0);
            acc1 = fmaf(R.x, wr[3].y, acc1);
            acc0 = fmaf(R.x, wr[4].x, acc0);
            acc1 = fmaf(R.y, wr[4].y, acc1);
        }
        __stcs((float2*)(po + (size_t)c * PLANE), make_float2(acc0, acc1));
    }
}

extern "C" void kernel_launch(void* const* d_in, const int* in_sizes, int n_in,
                              void* d_out, int out_size) {
    const float* in1 = (const float*)d_in[0];
    const float* in2 = (const float*)d_in[1];
    float* out = (float*)d_out;

    dim3 block(32, 8);
    dim3 grid(WDIM / TILE_W, HDIM / TILE_H, NDIM);  // 12 x 48 x 4
    lga_kernel<<<grid, block>>>(in1, in2, out);
}